// round 16
// baseline (speedup 1.0000x reference)
#include <cuda_runtime.h>
#include <math.h>
#include <limits.h>

// Problem constants (fixed by the reference setup_inputs)
#define BB    4
#define NN    8192
#define MM    8192
#define TPB   256
#define QPT   2
#define QBLK  (TPB * QPT)             // 512 queries per block
#define SPLIT 8
#define CH    (MM / SPLIT)            // 1024 context points per chunk
#define QB    (NN / QBLK)             // 16 query-blocks per batch

// Output layout: [unit BB*3*NN][cen BB*3*NN][pos BB*NN]
#define OFF_U 0
#define OFF_C (BB * 3 * NN)
#define OFF_P (2 * BB * 3 * NN)

// Scratch (allocation-free: __device__ globals)
__device__ float g_pd[3 * SPLIT * BB * NN];
__device__ int   g_pi[3 * SPLIT * BB * NN];
__device__ unsigned char g_mask[BB * NN];
__device__ int g_first[BB];

#define PD(k, s, q) g_pd[(((k) * SPLIT + (s)) * (BB * NN)) + (q)]
#define PI(k, s, q) g_pi[(((k) * SPLIT + (s)) * (BB * NN)) + (q)]

// ---- packed f32x2 helpers (Blackwell sm_100+): mul/add/fma only ----
typedef unsigned long long u64;

__device__ __forceinline__ u64 f2pk(float lo, float hi) {
    u64 r;
    asm("mov.b64 %0, {%1, %2};" : "=l"(r)
        : "r"(__float_as_uint(lo)), "r"(__float_as_uint(hi)));
    return r;
}
__device__ __forceinline__ void f2un(u64 v, float& lo, float& hi) {
    unsigned a, b;
    asm("mov.b64 {%0, %1}, %2;" : "=r"(a), "=r"(b) : "l"(v));
    lo = __uint_as_float(a); hi = __uint_as_float(b);
}
__device__ __forceinline__ u64 fma2(u64 a, u64 b, u64 c) {
    u64 r; asm("fma.rn.f32x2 %0, %1, %2, %3;" : "=l"(r) : "l"(a), "l"(b), "l"(c)); return r;
}

// Branchless stable top-3 insert over named state (strict '<': lowest-index
// ties kept when applied in ascending-j order, matching lax.top_k).
#define INS3(D0, D1, D2, I0, I1, I2, d, jj) {                                \
    bool lt2 = (d) < D2, lt1 = (d) < D1, lt0 = (d) < D0;                     \
    float nd2 = lt1 ? D1 : (d);  int ni2 = lt1 ? I1 : (jj);                  \
    float nd1 = lt0 ? D0 : (d);  int ni1 = lt0 ? I0 : (jj);                  \
    D2 = lt2 ? nd2 : D2;  I2 = lt2 ? ni2 : I2;                               \
    D1 = lt1 ? nd1 : D1;  I1 = lt1 ? ni1 : I1;                               \
    D0 = lt0 ? (d) : D0;  I0 = lt0 ? (jj) : I0;                              \
}

// 4-candidate insert with single-candidate fast path, over named state.
#define QINS(D0, D1, D2, I0, I1, I2, da, db, dc, dd, jb) {                   \
    bool pa = (da) < D2, pb = (db) < D2, pc = (dc) < D2, pd = (dd) < D2;     \
    int cnt = (int)pa + (int)pb + (int)pc + (int)pd;                         \
    if (cnt == 1) {                                                          \
        float ds = pa ? (da) : (pb ? (db) : (pc ? (dc) : (dd)));             \
        int   js = pa ? (jb) : (pb ? (jb) + 1 : (pc ? (jb) + 2 : (jb) + 3)); \
        INS3(D0, D1, D2, I0, I1, I2, ds, js);                                \
    } else {                                                                 \
        INS3(D0, D1, D2, I0, I1, I2, da, (jb));                              \
        INS3(D0, D1, D2, I0, I1, I2, db, (jb) + 1);                          \
        INS3(D0, D1, D2, I0, I1, I2, dc, (jb) + 2);                          \
        INS3(D0, D1, D2, I0, I1, I2, dd, (jb) + 3);                          \
    }                                                                        \
}

__global__ void __launch_bounds__(TPB)
surf_scan_kernel(const float* __restrict__ center,
                 const float* __restrict__ context)
{
    // Interleaved packed layout: per point-pair p (points 2p, 2p+1),
    // sD[4p..4p+3] = { (x0,x1), (y0,y1), (z0,z1), (w0,w1) }  (32 bytes).
    __shared__ __align__(16) u64 sD[(CH / 2) * 4];   // 16 KB

    // One-time scratch init for this replay (merge runs after scan completes)
    if (blockIdx.x < BB && threadIdx.x == 0) g_first[blockIdx.x] = INT_MAX;

    // blockIdx.x = ((b * QB) + qb) * SPLIT + s
    const int s  = blockIdx.x % SPLIT;
    const int r  = blockIdx.x / SPLIT;
    const int qb = r % QB;
    const int b  = r / QB;
    const int j0 = s * CH;

    // Load phase: pack into interleaved f32x2 words (8-byte granular writes)
    const float* ctx = context + (size_t)b * 3 * MM;
    for (int j = threadIdx.x; j < CH; j += TPB) {
        float x = ctx[j0 + j];
        float y = ctx[MM + j0 + j];
        float z = ctx[2 * MM + j0 + j];
        float w = x * x + y * y + z * z;
        const int p = j >> 1, l = j & 1;
        float* f = (float*)&sD[4 * p];
        f[l]     = x;   // (x0,x1)
        f[2 + l] = y;   // (y0,y1)
        f[4 + l] = z;   // (z0,z1)
        f[6 + l] = w;   // (w0,w1)
    }
    __syncthreads();

    // Two query points per thread: nA and nB = nA + TPB
    const int nA = qb * QBLK + threadIdx.x;
    const int nB = nA + TPB;
    const float* cenp = center + (size_t)b * 3 * NN;
    const float qxA = cenp[nA],          qxB = cenp[nB];
    const float qyA = cenp[NN + nA],     qyB = cenp[NN + nB];
    const float qzA = cenp[2 * NN + nA], qzB = cenp[2 * NN + nB];

    // d' = w - 2*dot (query-constant |c|^2 shift dropped; ranking identical)
    const u64 AX = f2pk(-2.0f * qxA, -2.0f * qxA);
    const u64 AY = f2pk(-2.0f * qyA, -2.0f * qyA);
    const u64 AZ = f2pk(-2.0f * qzA, -2.0f * qzA);
    const u64 BX = f2pk(-2.0f * qxB, -2.0f * qxB);
    const u64 BY = f2pk(-2.0f * qyB, -2.0f * qyB);
    const u64 BZ = f2pk(-2.0f * qzB, -2.0f * qzB);

    float A0 = INFINITY, A1 = INFINITY, A2 = INFINITY;
    float B0 = INFINITY, B1 = INFINITY, B2 = INFINITY;
    int   iA0 = 0, iA1 = 0, iA2 = 0;
    int   iB0 = 0, iB1 = 0, iB2 = 0;

    const ulonglong2* sV = (const ulonglong2*)sD;

    #pragma unroll 2
    for (int p = 0; p < CH / 2; p += 2) {     // 4 points, 2 queries / iter
        ulonglong2 a0 = sV[2 * p];            // {x01, y01}
        ulonglong2 a1 = sV[2 * p + 1];        // {z01, w01}
        ulonglong2 a2 = sV[2 * p + 2];        // {x23, y23}
        ulonglong2 a3 = sV[2 * p + 3];        // {z23, w23}

        // Query A
        u64 tA0 = fma2(AX, a0.x, a1.y);
        tA0 = fma2(AY, a0.y, tA0);
        u64 dA0 = fma2(AZ, a1.x, tA0);
        u64 tA1 = fma2(AX, a2.x, a3.y);
        tA1 = fma2(AY, a2.y, tA1);
        u64 dA1 = fma2(AZ, a3.x, tA1);

        // Query B
        u64 tB0 = fma2(BX, a0.x, a1.y);
        tB0 = fma2(BY, a0.y, tB0);
        u64 dB0 = fma2(BZ, a1.x, tB0);
        u64 tB1 = fma2(BX, a2.x, a3.y);
        tB1 = fma2(BY, a2.y, tB1);
        u64 dB1 = fma2(BZ, a3.x, tB1);

        float ea, eb, ec, ed, fa, fb, fc, fd;
        f2un(dA0, ea, eb);
        f2un(dA1, ec, ed);
        f2un(dB0, fa, fb);
        f2un(dB1, fc, fd);

        float mA = fminf(fminf(ea, eb), fminf(ec, ed));
        float mB = fminf(fminf(fa, fb), fminf(fc, fd));

        const int jj = j0 + 2 * p;
        if (mA < A2) {                        // rare
            QINS(A0, A1, A2, iA0, iA1, iA2, ea, eb, ec, ed, jj);
        }
        if (mB < B2) {                        // rare
            QINS(B0, B1, B2, iB0, iB1, iB2, fa, fb, fc, fd, jj);
        }
    }

    const int qA = b * NN + nA;
    const int qB_ = b * NN + nB;
    PD(0, s, qA) = A0;  PI(0, s, qA) = iA0;
    PD(1, s, qA) = A1;  PI(1, s, qA) = iA1;
    PD(2, s, qA) = A2;  PI(2, s, qA) = iA2;
    PD(0, s, qB_) = B0; PI(0, s, qB_) = iB0;
    PD(1, s, qB_) = B1; PI(1, s, qB_) = iB1;
    PD(2, s, qB_) = B2; PI(2, s, qB_) = iB2;
}

// Merge SPLIT partial triples per query, epilogue, mask, first-good-row.
// Partials are in the d' = w - 2*dot domain (consistent per query).
__global__ void __launch_bounds__(256)
surf_merge_kernel(const float* __restrict__ context,
                  float* __restrict__ out)
{
    const int q = blockIdx.x * blockDim.x + threadIdx.x;
    if (q >= BB * NN) return;
    const int b = q / NN;
    const int n = q % NN;

    float d0 = INFINITY, d1 = INFINITY, d2 = INFINITY;
    int   i0 = 0, i1 = 0, i2 = 0;

    // Ascending split order + rank order -> exact global-scan tie semantics.
    #pragma unroll
    for (int s = 0; s < SPLIT; s++) {
        #pragma unroll
        for (int k = 0; k < 3; k++) {
            float d  = PD(k, s, q);
            int   jj = PI(k, s, q);
            INS3(d0, d1, d2, i0, i1, i2, d, jj);
        }
    }

    const float* ctx = context + (size_t)b * 3 * MM;
    float g0x = ctx[i0], g0y = ctx[MM + i0], g0z = ctx[2 * MM + i0];
    float g1x = ctx[i1], g1y = ctx[MM + i1], g1z = ctx[2 * MM + i1];
    float g2x = ctx[i2], g2y = ctx[MM + i2], g2z = ctx[2 * MM + i2];

    float e1x = g1x - g0x, e1y = g1y - g0y, e1z = g1z - g0z;
    float e2x = g2x - g0x, e2y = g2y - g0y, e2z = g2z - g0z;

    float nx = e1y * e2z - e1z * e2y;
    float ny = e1z * e2x - e1x * e2z;
    float nz = e1x * e2y - e1y * e2x;

    float nrm = sqrtf(nx * nx + ny * ny + nz * nz);
    float ux = nx / nrm;
    float uy = ny / nrm;
    float uz = nz / nrm;

    float sg = (ux > 0.0f) ? 1.0f : -1.0f;   // NaN compares false -> -1
    ux *= sg; uy *= sg; uz *= sg;

    float cx = (g0x + g1x + g2x) / 3.0f;
    float cy = (g0y + g1y + g2y) / 3.0f;
    float cz = (g0z + g1z + g2z) / 3.0f;

    float pos = (ux * cx + uy * cy + uz * cz) / sqrtf(3.0f);

    bool bad = (ux != ux) || (uy != uy) || (uz != uz);
    g_mask[q] = bad ? 1 : 0;

    // first non-NaN row per batch: warp-reduce then one atomic per warp.
    // Block covers consecutive q within ONE batch (NN % 256 == 0).
    int v = bad ? INT_MAX : n;
    int wmin = __reduce_min_sync(0xffffffffu, v);
    if ((threadIdx.x & 31) == 0 && wmin != INT_MAX)
        atomicMin(&g_first[b], wmin);

    const size_t base = (size_t)b * 3 * NN + n;
    out[OFF_U + base]          = ux;
    out[OFF_U + base + NN]     = uy;
    out[OFF_U + base + 2 * NN] = uz;
    out[OFF_C + base]          = cx;
    out[OFF_C + base + NN]     = cy;
    out[OFF_C + base + 2 * NN] = cz;
    out[OFF_P + (size_t)b * NN + n] = pos;
}

// Rewrite masked rows with the first non-NaN row's values
__global__ void surf_fix_kernel(float* __restrict__ out)
{
    const int idx = blockIdx.x * blockDim.x + threadIdx.x;
    if (idx >= BB * NN) return;
    if (!g_mask[idx]) return;

    const int b = idx / NN;
    const int n = idx % NN;
    int f = g_first[b];
    if (f == INT_MAX) f = 0;   // all-masked: reference argmax(~mask) = 0

    const size_t src = (size_t)b * 3 * NN + f;
    const size_t dst = (size_t)b * 3 * NN + n;

    out[OFF_U + dst]          = out[OFF_U + src];
    out[OFF_U + dst + NN]     = out[OFF_U + src + NN];
    out[OFF_U + dst + 2 * NN] = out[OFF_U + src + 2 * NN];
    out[OFF_C + dst]          = out[OFF_C + src];
    out[OFF_C + dst + NN]     = out[OFF_C + src + NN];
    out[OFF_C + dst + 2 * NN] = out[OFF_C + src + 2 * NN];
    out[OFF_P + (size_t)b * NN + n] = out[OFF_P + (size_t)b * NN + f];
}

extern "C" void kernel_launch(void* const* d_in, const int* in_sizes, int n_in,
                              void* d_out, int out_size)
{
    const float* center  = (const float*)d_in[0];   // [B,3,N]
    const float* context = (const float*)d_in[1];   // [B,3,M]
    float* out = (float*)d_out;

    surf_scan_kernel<<<BB * QB * SPLIT, TPB>>>(center, context);
    surf_merge_kernel<<<(BB * NN + 255) / 256, 256>>>(context, out);
    surf_fix_kernel<<<(BB * NN + 255) / 256, 256>>>(out);
}

// round 17
// speedup vs baseline: 1.1796x; 1.1796x over previous
#include <cuda_runtime.h>
#include <math.h>
#include <limits.h>

// Problem constants (fixed by the reference setup_inputs)
#define BB    4
#define NN    8192
#define MM    8192
#define TPB   256
#define SPLIT 8
#define CH    (MM / SPLIT)            // 1024 context points per chunk
#define BPB   (NN / TPB)              // 32 query-blocks per batch

// Output layout: [unit BB*3*NN][cen BB*3*NN][pos BB*NN]
#define OFF_U 0
#define OFF_C (BB * 3 * NN)
#define OFF_P (2 * BB * 3 * NN)

// Scratch (allocation-free: __device__ globals)
__device__ float g_pd[3 * SPLIT * BB * NN];
__device__ int   g_pi[3 * SPLIT * BB * NN];
__device__ unsigned char g_mask[BB * NN];
__device__ int g_first[BB];

#define PD(k, s, q) g_pd[(((k) * SPLIT + (s)) * (BB * NN)) + (q)]
#define PI(k, s, q) g_pi[(((k) * SPLIT + (s)) * (BB * NN)) + (q)]

// ---- packed f32x2 helpers (Blackwell sm_100+): mul/add/fma only ----
typedef unsigned long long u64;

__device__ __forceinline__ u64 f2pk(float lo, float hi) {
    u64 r;
    asm("mov.b64 %0, {%1, %2};" : "=l"(r)
        : "r"(__float_as_uint(lo)), "r"(__float_as_uint(hi)));
    return r;
}
__device__ __forceinline__ void f2un(u64 v, float& lo, float& hi) {
    unsigned a, b;
    asm("mov.b64 {%0, %1}, %2;" : "=r"(a), "=r"(b) : "l"(v));
    lo = __uint_as_float(a); hi = __uint_as_float(b);
}
__device__ __forceinline__ u64 fma2(u64 a, u64 b, u64 c) {
    u64 r; asm("fma.rn.f32x2 %0, %1, %2, %3;" : "=l"(r) : "l"(a), "l"(b), "l"(c)); return r;
}

// 64-bit shared load at base+imm: result lands directly in the register pair
// consumed by fma2 ("l" operand) — no LDS.128->pair marshalling MOVs.
#define LDS64(dst, base, imm) \
    asm("ld.shared.b64 %0, [%1+" #imm "];" : "=l"(dst) : "r"(base))

// Branchless stable top-3 insert (FSETP+SEL). Strict '<' keeps the
// earlier-inserted entry on exact ties => apply in ascending-j order,
// matching lax.top_k.
#define INSB(d, jj) {                                                        \
    bool lt2 = (d) < d2, lt1 = (d) < d1, lt0 = (d) < d0;                     \
    float nd2 = lt1 ? d1 : (d);  int ni2 = lt1 ? i1 : (jj);                  \
    float nd1 = lt0 ? d0 : (d);  int ni1 = lt0 ? i0 : (jj);                  \
    d2 = lt2 ? nd2 : d2;  i2 = lt2 ? ni2 : i2;                               \
    d1 = lt1 ? nd1 : d1;  i1 = lt1 ? ni1 : i1;                               \
    d0 = lt0 ? (d) : d0;  i0 = lt0 ? (jj) : i0;                              \
}

__global__ void __launch_bounds__(TPB)
surf_scan_kernel(const float* __restrict__ center,
                 const float* __restrict__ context)
{
    // Interleaved packed layout: per point-pair p (points 2p, 2p+1),
    // sD[4p..4p+3] = { (x0,x1), (y0,y1), (z0,z1), (w0,w1) }  (32 bytes).
    __shared__ __align__(16) u64 sD[(CH / 2) * 4];   // 16 KB

    // One-time scratch init for this replay (merge runs after scan completes)
    if (blockIdx.x < BB && threadIdx.x == 0) g_first[blockIdx.x] = INT_MAX;

    // blockIdx.x = ((b * BPB) + qb) * SPLIT + s
    const int s  = blockIdx.x % SPLIT;
    const int r  = blockIdx.x / SPLIT;
    const int qb = r % BPB;
    const int b  = r / BPB;
    const int j0 = s * CH;

    // Load phase: pack into interleaved f32x2 words (8-byte granular writes)
    const float* ctx = context + (size_t)b * 3 * MM;
    for (int j = threadIdx.x; j < CH; j += TPB) {
        float x = ctx[j0 + j];
        float y = ctx[MM + j0 + j];
        float z = ctx[2 * MM + j0 + j];
        float w = x * x + y * y + z * z;
        const int p = j >> 1, l = j & 1;
        float* f = (float*)&sD[4 * p];
        f[l]     = x;   // (x0,x1)
        f[2 + l] = y;   // (y0,y1)
        f[4 + l] = z;   // (z0,z1)
        f[6 + l] = w;   // (w0,w1)
    }
    __syncthreads();

    // This thread's query point
    const int n = qb * TPB + threadIdx.x;
    const float* cenp = center + (size_t)b * 3 * NN;
    const float qx = cenp[n];
    const float qy = cenp[NN + n];
    const float qz = cenp[2 * NN + n];

    // d' = w - 2*dot (query-constant |c|^2 shift dropped; ranking identical)
    const u64 QXn = f2pk(-2.0f * qx, -2.0f * qx);
    const u64 QYn = f2pk(-2.0f * qy, -2.0f * qy);
    const u64 QZn = f2pk(-2.0f * qz, -2.0f * qz);

    float d0 = INFINITY, d1 = INFINITY, d2 = INFINITY;
    int   i0 = 0, i1 = 0, i2 = 0;

    // Shared-state-space base address for asm loads
    unsigned sbase = (unsigned)__cvta_generic_to_shared(sD);

    #pragma unroll 4
    for (int p = 0; p < CH / 2; p += 2, sbase += 64) {  // 4 points / iter
        u64 x01, y01, z01, w01, x23, y23, z23, w23;
        LDS64(x01, sbase, 0);
        LDS64(y01, sbase, 8);
        LDS64(z01, sbase, 16);
        LDS64(w01, sbase, 24);
        LDS64(x23, sbase, 32);
        LDS64(y23, sbase, 40);
        LDS64(z23, sbase, 48);
        LDS64(w23, sbase, 56);

        u64 t0 = fma2(QXn, x01, w01);         // -2qx*x + w
        t0 = fma2(QYn, y01, t0);
        u64 dp0 = fma2(QZn, z01, t0);

        u64 t1 = fma2(QXn, x23, w23);
        t1 = fma2(QYn, y23, t1);
        u64 dp1 = fma2(QZn, z23, t1);

        float da, db, dc, dd;
        f2un(dp0, da, db);
        f2un(dp1, dc, dd);

        float m = fminf(fminf(da, db), fminf(dc, dd));
        if (m < d2) {                         // rare (~5% of groups)
            const int jj = j0 + 2 * p;
            bool pa = da < d2, pb = db < d2, pc = dc < d2, pd = dd < d2;
            int cnt = (int)pa + (int)pb + (int)pc + (int)pd;
            if (cnt == 1) {
                // exactly one candidate: order-independent single insert
                float ds = pa ? da : (pb ? db : (pc ? dc : dd));
                int   js = pa ? jj : (pb ? jj + 1 : (pc ? jj + 2 : jj + 3));
                INSB(ds, js);
            } else {
                // ascending-j sequential inserts: exact tie semantics
                INSB(da, jj);
                INSB(db, jj + 1);
                INSB(dc, jj + 2);
                INSB(dd, jj + 3);
            }
        }
    }

    const int q = b * NN + n;
    PD(0, s, q) = d0;  PI(0, s, q) = i0;
    PD(1, s, q) = d1;  PI(1, s, q) = i1;
    PD(2, s, q) = d2;  PI(2, s, q) = i2;
}

// Merge SPLIT partial triples per query, epilogue, mask, first-good-row.
// Partials are in the d' = w - 2*dot domain (consistent per query).
__global__ void __launch_bounds__(256)
surf_merge_kernel(const float* __restrict__ context,
                  float* __restrict__ out)
{
    const int q = blockIdx.x * blockDim.x + threadIdx.x;
    if (q >= BB * NN) return;
    const int b = q / NN;
    const int n = q % NN;

    float d0 = INFINITY, d1 = INFINITY, d2 = INFINITY;
    int   i0 = 0, i1 = 0, i2 = 0;

    // Ascending split order + rank order -> exact global-scan tie semantics.
    #pragma unroll
    for (int s = 0; s < SPLIT; s++) {
        #pragma unroll
        for (int k = 0; k < 3; k++) {
            float d  = PD(k, s, q);
            int   jj = PI(k, s, q);
            INSB(d, jj);
        }
    }

    const float* ctx = context + (size_t)b * 3 * MM;
    float g0x = ctx[i0], g0y = ctx[MM + i0], g0z = ctx[2 * MM + i0];
    float g1x = ctx[i1], g1y = ctx[MM + i1], g1z = ctx[2 * MM + i1];
    float g2x = ctx[i2], g2y = ctx[MM + i2], g2z = ctx[2 * MM + i2];

    float e1x = g1x - g0x, e1y = g1y - g0y, e1z = g1z - g0z;
    float e2x = g2x - g0x, e2y = g2y - g0y, e2z = g2z - g0z;

    float nx = e1y * e2z - e1z * e2y;
    float ny = e1z * e2x - e1x * e2z;
    float nz = e1x * e2y - e1y * e2x;

    float nrm = sqrtf(nx * nx + ny * ny + nz * nz);
    float ux = nx / nrm;
    float uy = ny / nrm;
    float uz = nz / nrm;

    float sg = (ux > 0.0f) ? 1.0f : -1.0f;   // NaN compares false -> -1
    ux *= sg; uy *= sg; uz *= sg;

    float cx = (g0x + g1x + g2x) / 3.0f;
    float cy = (g0y + g1y + g2y) / 3.0f;
    float cz = (g0z + g1z + g2z) / 3.0f;

    float pos = (ux * cx + uy * cy + uz * cz) / sqrtf(3.0f);

    bool bad = (ux != ux) || (uy != uy) || (uz != uz);
    g_mask[q] = bad ? 1 : 0;

    // first non-NaN row per batch: warp-reduce then one atomic per warp.
    // Block covers consecutive q within ONE batch (NN % 256 == 0).
    int v = bad ? INT_MAX : n;
    int wmin = __reduce_min_sync(0xffffffffu, v);
    if ((threadIdx.x & 31) == 0 && wmin != INT_MAX)
        atomicMin(&g_first[b], wmin);

    const size_t base = (size_t)b * 3 * NN + n;
    out[OFF_U + base]          = ux;
    out[OFF_U + base + NN]     = uy;
    out[OFF_U + base + 2 * NN] = uz;
    out[OFF_C + base]          = cx;
    out[OFF_C + base + NN]     = cy;
    out[OFF_C + base + 2 * NN] = cz;
    out[OFF_P + (size_t)b * NN + n] = pos;
}

// Rewrite masked rows with the first non-NaN row's values
__global__ void surf_fix_kernel(float* __restrict__ out)
{
    const int idx = blockIdx.x * blockDim.x + threadIdx.x;
    if (idx >= BB * NN) return;
    if (!g_mask[idx]) return;

    const int b = idx / NN;
    const int n = idx % NN;
    int f = g_first[b];
    if (f == INT_MAX) f = 0;   // all-masked: reference argmax(~mask) = 0

    const size_t src = (size_t)b * 3 * NN + f;
    const size_t dst = (size_t)b * 3 * NN + n;

    out[OFF_U + dst]          = out[OFF_U + src];
    out[OFF_U + dst + NN]     = out[OFF_U + src + NN];
    out[OFF_U + dst + 2 * NN] = out[OFF_U + src + 2 * NN];
    out[OFF_C + dst]          = out[OFF_C + src];
    out[OFF_C + dst + NN]     = out[OFF_C + src + NN];
    out[OFF_C + dst + 2 * NN] = out[OFF_C + src + 2 * NN];
    out[OFF_P + (size_t)b * NN + n] = out[OFF_P + (size_t)b * NN + f];
}

extern "C" void kernel_launch(void* const* d_in, const int* in_sizes, int n_in,
                              void* d_out, int out_size)
{
    const float* center  = (const float*)d_in[0];   // [B,3,N]
    const float* context = (const float*)d_in[1];   // [B,3,M]
    float* out = (float*)d_out;

    surf_scan_kernel<<<BB * BPB * SPLIT, TPB>>>(center, context);
    surf_merge_kernel<<<(BB * NN + 255) / 256, 256>>>(context, out);
    surf_fix_kernel<<<(BB * NN + 255) / 256, 256>>>(out);
}